// round 6
// baseline (speedup 1.0000x reference)
#include <cuda_runtime.h>
#include <cuda_bf16.h>
#include <math.h>
#include <stdint.h>

// ---------------- problem constants ----------------
constexpr int CB    = 2;
constexpr int CQ    = 1024;
constexpr int CHID  = 2048;
constexpr int CNH   = 32;
constexpr int CNKV  = 8;
constexpr int CHD   = 64;
constexpr int CG    = 4;
constexpr int CKB   = 512;
constexpr int CTOPK = 100;
#define SCALE_L2E 0.18033688f     // 0.125 * log2(e)
#define KB_B2     2.3561430f      // log2(512/100)

// ---------------- fp32 scratch ----------------
__device__ float g_kbq [CB*CQ*CNH*CHD];        // KB query fp32 (for top-k selection)
__device__ float g_kbkv[CB*CKB*1024];          // [row][ kbk | kbv ] fp32 (for scores)
__device__ float g_qsum_part[CB*16*CNKV*CHD];
__device__ float g_qsum[CB*CNKV*CHD];
__device__ float g_scores[CB*CKB];
__device__ int   g_topidx[CB*CTOPK];

// ---------------- bf16 hi/lo split buffers ----------------
__device__ __nv_bfloat16 s_hs_h [CB*CQ*CHID],  s_hs_l [CB*CQ*CHID];
__device__ __nv_bfloat16 s_kb_h [CB*CKB*CHID], s_kb_l [CB*CKB*CHID];
__device__ __nv_bfloat16 s_at_h [CB*CQ*CHID],  s_at_l [CB*CQ*CHID];
__device__ __nv_bfloat16 s_wq_h [CHID*CHID],   s_wq_l [CHID*CHID];
__device__ __nv_bfloat16 s_wqn_h[CHID*CHID],   s_wqn_l[CHID*CHID];
__device__ __nv_bfloat16 s_wo_h [CHID*CHID],   s_wo_l [CHID*CHID];
__device__ __nv_bfloat16 s_wkv_h[CHID*1024],   s_wkv_l[CHID*1024];
__device__ __nv_bfloat16 s_wkb_h[CHID*1024],   s_wkb_l[CHID*1024];
// attention operands (Q pre-scaled into log2 domain, K/V roped/raw)
__device__ __nv_bfloat16 s_qh  [CB*CQ*CHID],   s_ql  [CB*CQ*CHID];
__device__ __nv_bfloat16 s_kbqh[CB*CQ*CHID],   s_kbql[CB*CQ*CHID];
__device__ __nv_bfloat16 s_kvh [CB*CQ*1024],   s_kvl [CB*CQ*1024];
__device__ __nv_bfloat16 s_kbkvh[CB*CKB*1024], s_kbkvl[CB*CKB*1024];

// ---------------- split: f32*scale -> bf16 hi + lo (strided output) ----------------
__global__ void split_kernel(const float* __restrict__ in,
                             __nv_bfloat16* __restrict__ oh, __nv_bfloat16* __restrict__ ol,
                             int cols, int ostride, int coff, float scale, int total4) {
    int i = blockIdx.x * blockDim.x + threadIdx.x;
    if (i >= total4) return;
    int c4pr = cols >> 2;
    int r = i / c4pr, c4 = i % c4pr;
    float4 v = ((const float4*)in)[i];
    float vv[4] = {v.x * scale, v.y * scale, v.z * scale, v.w * scale};
    __nv_bfloat16 h[4], l[4];
    #pragma unroll
    for (int j = 0; j < 4; j++) {
        h[j] = __float2bfloat16_rn(vv[j]);
        l[j] = __float2bfloat16_rn(vv[j] - __bfloat162float(h[j]));
    }
    size_t ob = (size_t)r * ostride + coff + c4 * 4;
    *(__nv_bfloat162*)&oh[ob]     = __nv_bfloat162(h[0], h[1]);
    *(__nv_bfloat162*)&oh[ob + 2] = __nv_bfloat162(h[2], h[3]);
    *(__nv_bfloat162*)&ol[ob]     = __nv_bfloat162(l[0], l[1]);
    *(__nv_bfloat162*)&ol[ob + 2] = __nv_bfloat162(l[2], l[3]);
}

// ---------------- common PTX helpers ----------------
__device__ __forceinline__ void cp_async16(uint32_t dst, const void* src) {
    asm volatile("cp.async.cg.shared.global [%0], [%1], 16;\n" :: "r"(dst), "l"(src));
}
__device__ __forceinline__ void mma16816(float* c, const unsigned* a, const unsigned* b) {
    asm volatile(
        "mma.sync.aligned.m16n8k16.row.col.f32.bf16.bf16.f32 "
        "{%0,%1,%2,%3}, {%4,%5,%6,%7}, {%8,%9}, {%0,%1,%2,%3};"
        : "+f"(c[0]), "+f"(c[1]), "+f"(c[2]), "+f"(c[3])
        : "r"(a[0]), "r"(a[1]), "r"(a[2]), "r"(a[3]), "r"(b[0]), "r"(b[1]));
}
#define LDSM4(R, addr) asm volatile( \
    "ldmatrix.sync.aligned.m8n8.x4.shared.b16 {%0,%1,%2,%3}, [%4];" \
    : "=r"((R)[0]), "=r"((R)[1]), "=r"((R)[2]), "=r"((R)[3]) : "r"(addr))
#define LDSM4T(R, addr) asm volatile( \
    "ldmatrix.sync.aligned.m8n8.x4.trans.shared.b16 {%0,%1,%2,%3}, [%4];" \
    : "=r"((R)[0]), "=r"((R)[1]), "=r"((R)[2]), "=r"((R)[3]) : "r"(addr))
__device__ __forceinline__ float fexp2(float x) {
    float y; asm("ex2.approx.ftz.f32 %0, %1;" : "=f"(y) : "f"(x)); return y;
}

// ---------------- tensor-core GEMM with fused epilogue ----------------
// C[M,N] = A[M,K] @ B[K,N]; 3-pass bf16 hi/lo; optional fused RoPE / fp32 write / hi-lo split write.
constexpr int GBK = 32, GSTG = 3;
constexpr int STAGE_BYTES = 32768;

__device__ __forceinline__ void gemm_issue_stage(
        uint32_t base, int tid,
        const __nv_bfloat16* Ah, const __nv_bfloat16* Al,
        const __nv_bfloat16* Bh, const __nv_bfloat16* Bl,
        int rb, int cb, int k0, int K, int N) {
    #pragma unroll
    for (int it = 0; it < 2; it++) {
        int i = tid + it * 256;
        int r = i >> 2, c = i & 3;
        uint32_t dst = base + r * 64 + (((c ^ ((r >> 1) & 3))) << 4);
        size_t so = (size_t)(rb + r) * K + k0 + c * 8;
        cp_async16(dst,        Ah + so);
        cp_async16(dst + 8192, Al + so);
    }
    #pragma unroll
    for (int it = 0; it < 2; it++) {
        int i = tid + it * 256;
        int r = i >> 4, cn = i & 15;
        uint32_t dst = base + 16384 + r * 256 + (((cn ^ (r & 7))) << 4);
        size_t so = (size_t)(k0 + r) * N + cb + cn * 8;
        cp_async16(dst,        Bh + so);
        cp_async16(dst + 8192, Bl + so);
    }
}

template<bool ROPE, bool WF32, bool WSPLIT>
__global__ __launch_bounds__(256)
void gemm_epi(const __nv_bfloat16* __restrict__ Ah, const __nv_bfloat16* __restrict__ Al,
              const __nv_bfloat16* __restrict__ Bh, const __nv_bfloat16* __restrict__ Bl,
              float* __restrict__ Cf,
              __nv_bfloat16* __restrict__ Oh, __nv_bfloat16* __restrict__ Ol,
              int M, int N, int K, int ropeN, float scale,
              const int* __restrict__ pos,
              const float* __restrict__ cosT, const float* __restrict__ sinT) {
    extern __shared__ char smem[];
    uint32_t sb = (uint32_t)__cvta_generic_to_shared(smem);
    const int tid = threadIdx.x, lane = tid & 31, wid = tid >> 5;
    const int wm = wid >> 1, wn = wid & 1;
    const int gid = lane >> 2, tig = lane & 3;
    const int rb = blockIdx.y * 128, cb = blockIdx.x * 128;

    float acc[2][8][4];
    #pragma unroll
    for (int mt = 0; mt < 2; mt++)
        #pragma unroll
        for (int nt = 0; nt < 8; nt++)
            #pragma unroll
            for (int i = 0; i < 4; i++) acc[mt][nt][i] = 0.f;

    const int nk = K / GBK;
    gemm_issue_stage(sb, tid, Ah, Al, Bh, Bl, rb, cb, 0, K, N);
    asm volatile("cp.async.commit_group;\n" ::);
    if (nk > 1) {
        gemm_issue_stage(sb + STAGE_BYTES, tid, Ah, Al, Bh, Bl, rb, cb, GBK, K, N);
    }
    asm volatile("cp.async.commit_group;\n" ::);

    const int sub = lane >> 3, li = lane & 7;
    const int arow_off = ((sub & 1) ? 8 : 0) + li;
    const int akc_off  = (sub >> 1) ? 8 : 0;
    const int bk_off   = ((sub & 1) ? 8 : 0) + li;
    const int bn_off   = (sub >> 1) ? 8 : 0;

    for (int i = 0; i < nk; i++) {
        asm volatile("cp.async.wait_group 1;\n" ::);
        __syncthreads();
        const int st = i % GSTG;
        const uint32_t abase = sb + st * STAGE_BYTES;
        const uint32_t bbase = abase + 16384;
        if (i + 2 < nk)
            gemm_issue_stage(sb + ((i + 2) % GSTG) * STAGE_BYTES, tid,
                             Ah, Al, Bh, Bl, rb, cb, (i + 2) * GBK, K, N);
        asm volatile("cp.async.commit_group;\n" ::);

        #pragma unroll
        for (int kk = 0; kk < GBK; kk += 16) {
            unsigned bh[8][2], bl[8][2];
            #pragma unroll
            for (int np = 0; np < 4; np++) {
                int n0 = wn * 64 + np * 16;
                int k  = kk + bk_off;
                int n  = n0 + bn_off;
                uint32_t addr = bbase + k * 256 + ((((n >> 3) ^ (k & 7))) << 4);
                unsigned r_[4];
                LDSM4T(r_, addr);
                bh[np*2][0] = r_[0]; bh[np*2][1] = r_[1]; bh[np*2+1][0] = r_[2]; bh[np*2+1][1] = r_[3];
                LDSM4T(r_, addr + 8192);
                bl[np*2][0] = r_[0]; bl[np*2][1] = r_[1]; bl[np*2+1][0] = r_[2]; bl[np*2+1][1] = r_[3];
            }
            #pragma unroll
            for (int mt = 0; mt < 2; mt++) {
                int r0 = wm * 32 + mt * 16;
                int row  = r0 + arow_off;
                int kcol = kk + akc_off;
                uint32_t aaddr = abase + row * 64 + ((((kcol >> 3) ^ ((row >> 1) & 3))) << 4);
                unsigned ah[4], al[4];
                LDSM4(ah, aaddr);
                LDSM4(al, aaddr + 8192);
                #pragma unroll
                for (int nt = 0; nt < 8; nt++) {
                    mma16816(acc[mt][nt], ah, bh[nt]);
                    mma16816(acc[mt][nt], ah, bl[nt]);
                    mma16816(acc[mt][nt], al, bh[nt]);
                }
            }
        }
        __syncthreads();
    }

    // ---- fused epilogue ----
    #pragma unroll
    for (int mt = 0; mt < 2; mt++) {
        const int row0 = rb + wm * 32 + mt * 16 + gid;
        const int row1 = row0 + 8;
        // RoPE in registers: head = 64 cols aligned with this warp's 64-wide tile
        if (ROPE) {
            const int cbase = cb + wn * 64;
            if (cbase < ropeN) {
                const int p0 = pos[row0] * 64, p1 = pos[row1] * 64;
                #pragma unroll
                for (int nt = 0; nt < 4; nt++) {
                    const int d0 = nt * 8 + 2 * tig;
                    float2 c0l = *(const float2*)&cosT[p0 + d0];
                    float2 s0l = *(const float2*)&sinT[p0 + d0];
                    float2 c0h = *(const float2*)&cosT[p0 + d0 + 32];
                    float2 s0h = *(const float2*)&sinT[p0 + d0 + 32];
                    float2 c1l = *(const float2*)&cosT[p1 + d0];
                    float2 s1l = *(const float2*)&sinT[p1 + d0];
                    float2 c1h = *(const float2*)&cosT[p1 + d0 + 32];
                    float2 s1h = *(const float2*)&sinT[p1 + d0 + 32];
                    // row0, cols d0 / d0+1
                    float x1, x2;
                    x1 = acc[mt][nt][0]; x2 = acc[mt][nt+4][0];
                    acc[mt][nt][0]   = x1 * c0l.x - x2 * s0l.x;
                    acc[mt][nt+4][0] = x2 * c0h.x + x1 * s0h.x;
                    x1 = acc[mt][nt][1]; x2 = acc[mt][nt+4][1];
                    acc[mt][nt][1]   = x1 * c0l.y - x2 * s0l.y;
                    acc[mt][nt+4][1] = x2 * c0h.y + x1 * s0h.y;
                    // row1
                    x1 = acc[mt][nt][2]; x2 = acc[mt][nt+4][2];
                    acc[mt][nt][2]   = x1 * c1l.x - x2 * s1l.x;
                    acc[mt][nt+4][2] = x2 * c1h.x + x1 * s1h.x;
                    x1 = acc[mt][nt][3]; x2 = acc[mt][nt+4][3];
                    acc[mt][nt][3]   = x1 * c1l.y - x2 * s1l.y;
                    acc[mt][nt+4][3] = x2 * c1h.y + x1 * s1h.y;
                }
            }
        }
        #pragma unroll
        for (int nt = 0; nt < 8; nt++) {
            const int col = cb + wn * 64 + nt * 8 + tig * 2;
            if (WF32) {
                *(float2*)&Cf[(size_t)row0 * N + col] = make_float2(acc[mt][nt][0], acc[mt][nt][1]);
                *(float2*)&Cf[(size_t)row1 * N + col] = make_float2(acc[mt][nt][2], acc[mt][nt][3]);
            }
            if (WSPLIT) {
                float y0 = acc[mt][nt][0] * scale, y1 = acc[mt][nt][1] * scale;
                float y2 = acc[mt][nt][2] * scale, y3 = acc[mt][nt][3] * scale;
                __nv_bfloat162 h0 = __floats2bfloat162_rn(y0, y1);
                float2 f0 = __bfloat1622float2(h0);
                __nv_bfloat162 l0 = __floats2bfloat162_rn(y0 - f0.x, y1 - f0.y);
                __nv_bfloat162 h1 = __floats2bfloat162_rn(y2, y3);
                float2 f1 = __bfloat1622float2(h1);
                __nv_bfloat162 l1 = __floats2bfloat162_rn(y2 - f1.x, y3 - f1.y);
                *(__nv_bfloat162*)&Oh[(size_t)row0 * N + col] = h0;
                *(__nv_bfloat162*)&Ol[(size_t)row0 * N + col] = l0;
                *(__nv_bfloat162*)&Oh[(size_t)row1 * N + col] = h1;
                *(__nv_bfloat162*)&Ol[(size_t)row1 * N + col] = l1;
            }
        }
    }
}

// ---------------- KB selection ----------------
__global__ void qsum_partial_kernel() {
    int b  = blockIdx.x, ch = blockIdx.y;
    int c  = threadIdx.x;
    int kh = c / CHD, dd = c % CHD;
    float s = 0.f;
    for (int q = ch * 64; q < ch * 64 + 64; q++) {
        const float* row = g_kbq + (size_t)(b * CQ + q) * (CNH * CHD);
        #pragma unroll
        for (int g = 0; g < CG; g++) s += row[(kh * CG + g) * CHD + dd];
    }
    g_qsum_part[(b * 16 + ch) * 512 + c] = s;
}
__global__ void qsum_combine_kernel() {
    int b = blockIdx.x, c = threadIdx.x;
    float s = 0.f;
    #pragma unroll
    for (int ch = 0; ch < 16; ch++) s += g_qsum_part[(b * 16 + ch) * 512 + c];
    g_qsum[b * 512 + c] = s;
}
__global__ void scores_kernel() {
    int gw = blockIdx.x * 8 + (threadIdx.x >> 5);
    int l  = threadIdx.x & 31;
    int b  = gw >> 9, n = gw & 511;
    const float* kr = g_kbkv + (size_t)(b * CKB + n) * 1024;
    const float* qs = g_qsum + b * 512;
    float s = 0.f;
    #pragma unroll
    for (int i = l; i < 512; i += 32) s = fmaf(kr[i], qs[i], s);
    #pragma unroll
    for (int o = 16; o > 0; o >>= 1) s += __shfl_xor_sync(0xffffffffu, s, o);
    if (l == 0) g_scores[b * CKB + n] = s;
}
// single warp per batch; no block barriers
__global__ void topk_kernel() {
    int b = blockIdx.x, l = threadIdx.x;
    __shared__ float sv[CKB];
    for (int i = l; i < CKB; i += 32) sv[i] = g_scores[b * CKB + i];
    __syncwarp();
    for (int t = 0; t < CTOPK; t++) {
        float v = -3.0e38f; int idx = 0x7fffffff;
        for (int i = l; i < CKB; i += 32) {
            float x = sv[i];
            if (x > v || (x == v && i < idx)) { v = x; idx = i; }
        }
        #pragma unroll
        for (int o = 16; o > 0; o >>= 1) {
            float ov = __shfl_xor_sync(0xffffffffu, v, o);
            int   oi = __shfl_xor_sync(0xffffffffu, idx, o);
            if (ov > v || (ov == v && oi < idx)) { v = ov; idx = oi; }
        }
        if (l == 0) { g_topidx[b * CTOPK + t] = idx; sv[idx] = -3.0e38f; }
        __syncwarp();
    }
}

// ---------------- tensor-core fused flash attention (mma.sync) ----------------
constexpr int ATT_SMEM = 16384 + 2 * 32768;

__device__ __forceinline__ void attn_load_tile(uint32_t st, int b, int kh, int ph2, int t, int tid) {
    for (int i = tid; i < 512; i += 128) {
        int r = i >> 3, c = i & 7;
        int kg = t * 64 + r;
        const __nv_bfloat16 *H, *L;
        size_t base;
        if (ph2 == 0) {
            int n = (kg < CTOPK) ? g_topidx[b * CTOPK + kg] : 0;
            base = (size_t)(b * CKB + n) * 1024 + kh * 64;
            H = s_kbkvh; L = s_kbkvl;
        } else {
            base = (size_t)(b * CQ + kg) * 1024 + kh * 64;
            H = s_kvh; L = s_kvl;
        }
        uint32_t d = st + r * 128 + ((c ^ (r & 7)) << 4);
        cp_async16(d,         H + base + c * 8);
        cp_async16(d + 8192,  L + base + c * 8);
        cp_async16(d + 16384, H + base + 512 + c * 8);
        cp_async16(d + 24576, L + base + 512 + c * 8);
    }
}

__global__ __launch_bounds__(128) void attn_tc_kernel() {
    extern __shared__ char asmem[];
    uint32_t sq = (uint32_t)__cvta_generic_to_shared(asmem);
    const int tid = threadIdx.x, lane = tid & 31, w = tid >> 5;
    const int gid = lane >> 2, tig = lane & 3;
    const int sub = lane >> 3, li = lane & 7;
    const int qt = blockIdx.x, h = blockIdx.y, b = blockIdx.z;
    const int kh = h >> 2;
    const int q0 = qt * 64;

    float m0 = -1e30f, m1 = -1e30f, l0 = 0.f, l1 = 0.f;
    float oacc[8][4];
    #pragma unroll
    for (int nt = 0; nt < 8; nt++)
        #pragma unroll
        for (int c = 0; c < 4; c++) oacc[nt][c] = 0.f;

    for (int ph2 = 0; ph2 < 2; ph2++) {
        __syncthreads();
        const __nv_bfloat16* Qh = ph2 ? s_qh : s_kbqh;
        const __nv_bfloat16* Ql = ph2 ? s_ql : s_kbql;
        for (int i = tid; i < 512; i += 128) {
            int r = i >> 3, c = i & 7;
            uint32_t dst = sq + r * 128 + ((c ^ (r & 7)) << 4);
            size_t src = (size_t)(b * CQ + q0 + r) * 2048 + h * 64 + c * 8;
            cp_async16(dst,        Qh + src);
            cp_async16(dst + 8192, Ql + src);
        }
        const int ntiles = ph2 ? (qt + 1) : 2;
        attn_load_tile(sq + 16384, b, kh, ph2, 0, tid);
        asm volatile("cp.async.commit_group;\n" ::);

        for (int t = 0; t < ntiles; t++) {
            asm volatile("cp.async.wait_group 0;\n" ::);
            __syncthreads();
            if (t + 1 < ntiles) {
                attn_load_tile(sq + 16384 + ((t + 1) & 1) * 32768, b, kh, ph2, t + 1, tid);
                asm volatile("cp.async.commit_group;\n" ::);
            }
            const uint32_t stK = sq + 16384 + (t & 1) * 32768;
            const uint32_t stV = stK + 16384;

            float sacc[8][4];
            #pragma unroll
            for (int nt = 0; nt < 8; nt++)
                #pragma unroll
                for (int c = 0; c < 4; c++) sacc[nt][c] = 0.f;

            #pragma unroll
            for (int k16 = 0; k16 < 4; k16++) {
                int kk = k16 * 16;
                unsigned qa_h[4], qa_l[4];
                {
                    int row = w * 16 + (sub & 1) * 8 + li;
                    int ch  = (kk >> 3) + (sub >> 1);
                    uint32_t a = sq + row * 128 + ((ch ^ (row & 7)) << 4);
                    LDSM4(qa_h, a);
                    LDSM4(qa_l, a + 8192);
                }
                unsigned kb_h[8][2], kb_l[8][2];
                #pragma unroll
                for (int nt2 = 0; nt2 < 4; nt2++) {
                    int n  = nt2 * 16 + (sub >> 1) * 8 + li;
                    int ch = (kk >> 3) + (sub & 1);
                    uint32_t a = stK + n * 128 + ((ch ^ (n & 7)) << 4);
                    unsigned r_[4];
                    LDSM4(r_, a);
                    kb_h[nt2*2][0] = r_[0]; kb_h[nt2*2][1] = r_[1];
                    kb_h[nt2*2+1][0] = r_[2]; kb_h[nt2*2+1][1] = r_[3];
                    LDSM4(r_, a + 8192);
                    kb_l[nt2*2][0] = r_[0]; kb_l[nt2*2][1] = r_[1];
                    kb_l[nt2*2+1][0] = r_[2]; kb_l[nt2*2+1][1] = r_[3];
                }
                #pragma unroll
                for (int nt = 0; nt < 8; nt++) {
                    mma16816(sacc[nt], qa_h, kb_h[nt]);
                    mma16816(sacc[nt], qa_h, kb_l[nt]);
                    mma16816(sacc[nt], qa_l, kb_h[nt]);
                }
            }

            if (ph2 == 0) {
                #pragma unroll
                for (int nt = 0; nt < 8; nt++) {
                    int kg = t * 64 + nt * 8 + 2 * tig;
                    sacc[nt][0] = (kg     < CTOPK) ? sacc[nt][0] + KB_B2 : -1e30f;
                    sacc[nt][1] = (kg + 1 < CTOPK) ? sacc[nt][1] + KB_B2 : -1e30f;
                    sacc[nt][2] = (kg     < CTOPK) ? sacc[nt][2] + KB_B2 : -1e30f;
                    sacc[nt][3] = (kg + 1 < CTOPK) ? sacc[nt][3] + KB_B2 : -1e30f;
                }
            } else if (t == qt) {
                int rq0 = q0 + w * 16 + gid, rq1 = rq0 + 8;
                #pragma unroll
                for (int nt = 0; nt < 8; nt++) {
                    int kg = t * 64 + nt * 8 + 2 * tig;
                    if (kg     > rq0) sacc[nt][0] = -1e30f;
                    if (kg + 1 > rq0) sacc[nt][1] = -1e30f;
                    if (kg     > rq1) sacc[nt][2] = -1e30f;
                    if (kg + 1 > rq1) sacc[nt][3] = -1e30f;
                }
            }

            float mx0 = -1e30f, mx1 = -1e30f;
            #pragma unroll
            for (int nt = 0; nt < 8; nt++) {
                mx0 = fmaxf(mx0, fmaxf(sacc[nt][0], sacc[nt][1]));
                mx1 = fmaxf(mx1, fmaxf(sacc[nt][2], sacc[nt][3]));
            }
            mx0 = fmaxf(mx0, __shfl_xor_sync(0xffffffffu, mx0, 1));
            mx0 = fmaxf(mx0, __shfl_xor_sync(0xffffffffu, mx0, 2));
            mx1 = fmaxf(mx1, __shfl_xor_sync(0xffffffffu, mx1, 1));
            mx1 = fmaxf(mx1, __shfl_xor_sync(0xffffffffu, mx1, 2));
            float mn0 = fmaxf(m0, mx0), mn1 = fmaxf(m1, mx1);
            float cr0 = fexp2(m0 - mn0), cr1 = fexp2(m1 - mn1);
            float sum0 = 0.f, sum1 = 0.f;
            #pragma unroll
            for (int nt = 0; nt < 8; nt++) {
                sacc[nt][0] = fexp2(sacc[nt][0] - mn0);
                sacc[nt][1] = fexp2(sacc[nt][1] - mn0);
                sacc[nt][2] = fexp2(sacc[nt][2] - mn1);
                sacc[nt][3] = fexp2(sacc[nt][3] - mn1);
                sum0 += sacc[nt][0] + sacc[nt][1];
                sum1 += sacc[nt][2] + sacc[nt][3];
                oacc[nt][0] *= cr0; oacc[nt][1] *= cr0;
                oacc[nt][2] *= cr1; oacc[nt][3] *= cr1;
            }
            sum0 += __shfl_xor_sync(0xffffffffu, sum0, 1);
            sum0 += __shfl_xor_sync(0xffffffffu, sum0, 2);
            sum1 += __shfl_xor_sync(0xffffffffu, sum1, 1);
            sum1 += __shfl_xor_sync(0xffffffffu, sum1, 2);
            l0 = l0 * cr0 + sum0;
            l1 = l1 * cr1 + sum1;
            m0 = mn0; m1 = mn1;

            #pragma unroll
            for (int j = 0; j < 4; j++) {
                unsigned pa_h[4], pa_l[4];
                #pragma unroll
                for (int half = 0; half < 2; half++) {
                    float x0 = sacc[2*j+half][0], x1 = sacc[2*j+half][1];
                    float x2 = sacc[2*j+half][2], x3 = sacc[2*j+half][3];
                    __nv_bfloat162 hA = __floats2bfloat162_rn(x0, x1);
                    __nv_bfloat162 hB = __floats2bfloat162_rn(x2, x3);
                    float2 fA = __bfloat1622float2(hA), fB = __bfloat1622float2(hB);
                    __nv_bfloat162 lA = __floats2bfloat162_rn(x0 - fA.x, x1 - fA.y);
                    __nv_bfloat162 lB = __floats2bfloat162_rn(x2 - fB.x, x3 - fB.y);
                    pa_h[half*2]     = *(unsigned*)&hA;
                    pa_h[half*2 + 1] = *(unsigned*)&hB;
                    pa_l[half*2]     = *(unsigned*)&lA;
                    pa_l[half*2 + 1] = *(unsigned*)&lB;
                }
                unsigned vb_h[8][2], vb_l[8][2];
                #pragma unroll
                for (int nt2 = 0; nt2 < 4; nt2++) {
                    int k  = j * 16 + (sub & 1) * 8 + li;
                    int ch = nt2 * 2 + (sub >> 1);
                    uint32_t a = stV + k * 128 + ((ch ^ (k & 7)) << 4);
                    unsigned r_[4];
                    LDSM4T(r_, a);
                    vb_h[nt2*2][0] = r_[0]; vb_h[nt2*2][1] = r_[1];
                    vb_h[nt2*2+1][0] = r_[2]; vb_h[nt2*2+1][1] = r_[3];
                    LDSM4T(r_, a + 8192);
                    vb_l[nt2*2][0] = r_[0]; vb_l[nt2*2][1] = r_[1];
                    vb_l[nt2*2+1][0] = r_[2]; vb_l[nt2*2+1][1] = r_[3];
                }
                #pragma unroll
                for (int nt = 0; nt < 8; nt++) {
                    mma16816(oacc[nt], pa_h, vb_h[nt]);
                    mma16816(oacc[nt], pa_h, vb_l[nt]);
                    mma16816(oacc[nt], pa_l, vb_h[nt]);
                }
            }
        }
    }

    float i0 = 1.f / l0, i1 = 1.f / l1;
    size_t row0 = (size_t)(b * CQ + q0 + w * 16 + gid) * 2048;
    size_t row1 = row0 + 8 * 2048;
    #pragma unroll
    for (int nt = 0; nt < 8; nt++) {
        int col = h * 64 + nt * 8 + 2 * tig;
        float y0 = oacc[nt][0] * i0, y1 = oacc[nt][1] * i0;
        float y2 = oacc[nt][2] * i1, y3 = oacc[nt][3] * i1;
        __nv_bfloat162 h0 = __floats2bfloat162_rn(y0, y1);
        float2 f0 = __bfloat1622float2(h0);
        __nv_bfloat162 lo0 = __floats2bfloat162_rn(y0 - f0.x, y1 - f0.y);
        __nv_bfloat162 h1v = __floats2bfloat162_rn(y2, y3);
        float2 f1 = __bfloat1622float2(h1v);
        __nv_bfloat162 lo1 = __floats2bfloat162_rn(y2 - f1.x, y3 - f1.y);
        *(__nv_bfloat162*)&s_at_h[row0 + col] = h0;
        *(__nv_bfloat162*)&s_at_l[row0 + col] = lo0;
        *(__nv_bfloat162*)&s_at_h[row1 + col] = h1v;
        *(__nv_bfloat162*)&s_at_l[row1 + col] = lo1;
    }
}

// ---------------- launch ----------------
static inline void launch_split(const float* in, __nv_bfloat16* oh, __nv_bfloat16* ol,
                                int rows, int cols, int ostride, int coff, float scale) {
    int total4 = rows * cols / 4;
    split_kernel<<<(total4 + 255) / 256, 256>>>(in, oh, ol, cols, ostride, coff, scale, total4);
}

extern "C" void kernel_launch(void* const* d_in, const int* in_sizes, int n_in,
                              void* d_out, int out_size) {
    const float* hs   = (const float*)d_in[0];
    const float* kb   = (const float*)d_in[1];
    const float* Wq   = (const float*)d_in[2];
    const float* Wk   = (const float*)d_in[3];
    const float* Wv   = (const float*)d_in[4];
    const float* Wo   = (const float*)d_in[5];
    const float* Wqn  = (const float*)d_in[6];
    const float* Wkbk = (const float*)d_in[7];
    const float* Wkbv = (const float*)d_in[8];
    const float* cosT = (const float*)d_in[9];
    const float* sinT = (const float*)d_in[10];
    const int*   pos  = (const int*)d_in[12];
    float* out = (float*)d_out;

    float *pkbq, *pkbkv;
    cudaGetSymbolAddress((void**)&pkbq,  g_kbq);
    cudaGetSymbolAddress((void**)&pkbkv, g_kbkv);

    __nv_bfloat16 *hs_h, *hs_l, *kb_h, *kb_l, *at_h, *at_l;
    __nv_bfloat16 *wq_h, *wq_l, *wqn_h, *wqn_l, *wo_h, *wo_l, *wkv_h, *wkv_l, *wkb_h, *wkb_l;
    __nv_bfloat16 *qh, *ql, *kbqh, *kbql, *kvh, *kvl, *kbkvh, *kbkvl;
    cudaGetSymbolAddress((void**)&hs_h,  s_hs_h);  cudaGetSymbolAddress((void**)&hs_l,  s_hs_l);
    cudaGetSymbolAddress((void**)&kb_h,  s_kb_h);  cudaGetSymbolAddress((void**)&kb_l,  s_kb_l);
    cudaGetSymbolAddress((void**)&at_h,  s_at_h);  cudaGetSymbolAddress((void**)&at_l,  s_at_l);
    cudaGetSymbolAddress((void**)&wq_h,  s_wq_h);  cudaGetSymbolAddress((void**)&wq_l,  s_wq_l);
    cudaGetSymbolAddress((void**)&wqn_h, s_wqn_h); cudaGetSymbolAddress((void**)&wqn_l, s_wqn_l);
    cudaGetSymbolAddress((void**)&wo_h,  s_wo_h);  cudaGetSymbolAddress((void**)&wo_l,  s_wo_l);
    cudaGetSymbolAddress((void**)&wkv_h, s_wkv_h); cudaGetSymbolAddress((void**)&wkv_l, s_wkv_l);
    cudaGetSymbolAddress((void**)&wkb_h, s_wkb_h); cudaGetSymbolAddress((void**)&wkb_l, s_wkb_l);
    cudaGetSymbolAddress((void**)&qh,    s_qh);    cudaGetSymbolAddress((void**)&ql,    s_ql);
    cudaGetSymbolAddress((void**)&kbqh,  s_kbqh);  cudaGetSymbolAddress((void**)&kbql,  s_kbql);
    cudaGetSymbolAddress((void**)&kvh,   s_kvh);   cudaGetSymbolAddress((void**)&kvl,   s_kvl);
    cudaGetSymbolAddress((void**)&kbkvh, s_kbkvh); cudaGetSymbolAddress((void**)&kbkvl, s_kbkvl);

    static int attr_set = 0;
    if (!attr_set) {
        cudaFuncSetAttribute(gemm_epi<true,false,true>,  cudaFuncAttributeMaxDynamicSharedMemorySize, GSTG * STAGE_BYTES);
        cudaFuncSetAttribute(gemm_epi<false,true,true>,  cudaFuncAttributeMaxDynamicSharedMemorySize, GSTG * STAGE_BYTES);
        cudaFuncSetAttribute(gemm_epi<false,true,false>, cudaFuncAttributeMaxDynamicSharedMemorySize, GSTG * STAGE_BYTES);
        cudaFuncSetAttribute(attn_tc_kernel, cudaFuncAttributeMaxDynamicSharedMemorySize, ATT_SMEM);
        attr_set = 1;
    }

    const int M = CB * CQ;   // 2048
    const int SMEM = GSTG * STAGE_BYTES;

    // ---- input/weight splits ----
    launch_split(hs,   hs_h,  hs_l,  M,      CHID, CHID, 0,   1.f);
    launch_split(kb,   kb_h,  kb_l,  CB*CKB, CHID, CHID, 0,   1.f);
    launch_split(Wq,   wq_h,  wq_l,  CHID,   CHID, CHID, 0,   1.f);
    launch_split(Wqn,  wqn_h, wqn_l, CHID,   CHID, CHID, 0,   1.f);
    launch_split(Wo,   wo_h,  wo_l,  CHID,   CHID, CHID, 0,   1.f);
    launch_split(Wk,   wkv_h, wkv_l, CHID,   512,  1024, 0,   1.f);
    launch_split(Wv,   wkv_h, wkv_l, CHID,   512,  1024, 512, 1.f);
    launch_split(Wkbk, wkb_h, wkb_l, CHID,   512,  1024, 0,   1.f);
    launch_split(Wkbv, wkb_h, wkb_l, CHID,   512,  1024, 512, 1.f);

    // ---- projections with fused epilogues ----
    // Q: rope(all 2048 cols) + scale + split
    gemm_epi<true,false,true><<<dim3(CHID/128, M/128), 256, SMEM>>>(
        hs_h, hs_l, wq_h, wq_l, nullptr, qh, ql, M, CHID, CHID, CHID, SCALE_L2E, pos, cosT, sinT);
    // kbq: fp32 (for selection) + scaled split
    gemm_epi<false,true,true><<<dim3(CHID/128, M/128), 256, SMEM>>>(
        hs_h, hs_l, wqn_h, wqn_l, pkbq, kbqh, kbql, M, CHID, CHID, 0, SCALE_L2E, pos, cosT, sinT);
    // kv: rope on k half (cols < 512) + split
    gemm_epi<true,false,true><<<dim3(1024/128, M/128), 256, SMEM>>>(
        hs_h, hs_l, wkv_h, wkv_l, nullptr, kvh, kvl, M, 1024, CHID, 512, 1.f, pos, cosT, sinT);
    // kbkv: fp32 (for scores) + split
    gemm_epi<false,true,true><<<dim3(1024/128, (CB*CKB)/128), 256, SMEM>>>(
        kb_h, kb_l, wkb_h, wkb_l, pkbkv, kbkvh, kbkvl, CB*CKB, 1024, CHID, 0, 1.f, pos, cosT, sinT);

    // ---- KB top-k ----
    qsum_partial_kernel<<<dim3(CB, 16), 512>>>();
    qsum_combine_kernel<<<CB, 512>>>();
    scores_kernel<<<(CB * CKB) / 8, 256>>>();
    topk_kernel<<<CB, 32>>>();

    // ---- attention ----
    attn_tc_kernel<<<dim3(CQ / 64, CNH, CB), 128, ATT_SMEM>>>();

    // ---- output projection ----
    gemm_epi<false,true,false><<<dim3(CHID/128, M/128), 256, SMEM>>>(
        at_h, at_l, wo_h, wo_l, out, nullptr, nullptr, M, CHID, CHID, 0, 1.f, pos, cosT, sinT);
}

// round 7
// speedup vs baseline: 1.0768x; 1.0768x over previous
#include <cuda_runtime.h>
#include <cuda_bf16.h>
#include <math.h>
#include <stdint.h>

// ---------------- problem constants ----------------
constexpr int CB    = 2;
constexpr int CQ    = 1024;
constexpr int CHID  = 2048;
constexpr int CNH   = 32;
constexpr int CNKV  = 8;
constexpr int CHD   = 64;
constexpr int CG    = 4;
constexpr int CKB   = 512;
constexpr int CTOPK = 100;
#define SCALE_L2E 0.18033688f     // 0.125 * log2(e)
#define KB_B2     2.3561430f      // log2(512/100)

// ---------------- fp32 scratch ----------------
__device__ float g_kbq [CB*CQ*CNH*CHD];        // KB query fp32 (top-k selection)
__device__ float g_kbkv[CB*CKB*1024];          // [row][ kbk | kbv ] fp32 (scores)
__device__ float g_qsum_part[CB*16*CNKV*CHD];
__device__ float g_qsum[CB*CNKV*CHD];
__device__ float g_scores[CB*CKB];
__device__ int   g_topidx[CB*CTOPK];

// ---------------- bf16 hi/lo buffers ----------------
__device__ __nv_bfloat16 s_hs_h [CB*CQ*CHID],  s_hs_l [CB*CQ*CHID];
__device__ __nv_bfloat16 s_kb_h [CB*CKB*CHID], s_kb_l [CB*CKB*CHID];
__device__ __nv_bfloat16 s_at_h [CB*CQ*CHID],  s_at_l [CB*CQ*CHID];
__device__ __nv_bfloat16 s_wcomb_h[CHID*5120], s_wcomb_l[CHID*5120]; // [K][Wq|Wqn|Wk|Wv]
__device__ __nv_bfloat16 s_wo_h [CHID*CHID],   s_wo_l [CHID*CHID];
__device__ __nv_bfloat16 s_wkb_h[CHID*1024],   s_wkb_l[CHID*1024];   // [K][Wkbk|Wkbv]
// attention operands
__device__ __nv_bfloat16 s_qh  [CB*CQ*CHID],   s_ql  [CB*CQ*CHID];
__device__ __nv_bfloat16 s_kbqh[CB*CQ*CHID],   s_kbql[CB*CQ*CHID];
__device__ __nv_bfloat16 s_kvh [CB*CQ*1024],   s_kvl [CB*CQ*1024];
__device__ __nv_bfloat16 s_kbkvh[CB*CKB*1024], s_kbkvl[CB*CKB*1024];

// ---------------- common PTX helpers ----------------
__device__ __forceinline__ void cp_async16(uint32_t dst, const void* src) {
    asm volatile("cp.async.cg.shared.global [%0], [%1], 16;\n" :: "r"(dst), "l"(src));
}
__device__ __forceinline__ void mma16816(float* c, const unsigned* a, const unsigned* b) {
    asm volatile(
        "mma.sync.aligned.m16n8k16.row.col.f32.bf16.bf16.f32 "
        "{%0,%1,%2,%3}, {%4,%5,%6,%7}, {%8,%9}, {%0,%1,%2,%3};"
        : "+f"(c[0]), "+f"(c[1]), "+f"(c[2]), "+f"(c[3])
        : "r"(a[0]), "r"(a[1]), "r"(a[2]), "r"(a[3]), "r"(b[0]), "r"(b[1]));
}
#define LDSM4(R, addr) asm volatile( \
    "ldmatrix.sync.aligned.m8n8.x4.shared.b16 {%0,%1,%2,%3}, [%4];" \
    : "=r"((R)[0]), "=r"((R)[1]), "=r"((R)[2]), "=r"((R)[3]) : "r"(addr))
#define LDSM4T(R, addr) asm volatile( \
    "ldmatrix.sync.aligned.m8n8.x4.trans.shared.b16 {%0,%1,%2,%3}, [%4];" \
    : "=r"((R)[0]), "=r"((R)[1]), "=r"((R)[2]), "=r"((R)[3]) : "r"(addr))
__device__ __forceinline__ float fexp2(float x) {
    float y; asm("ex2.approx.ftz.f32 %0, %1;" : "=f"(y) : "f"(x)); return y;
}

// ---------------- mega split: all inputs+weights, one launch ----------------
// Each block = 256 float4s; all segments divide evenly.
__global__ __launch_bounds__(256)
void splitall_kernel(const float* __restrict__ hs, const float* __restrict__ kb,
                     const float* __restrict__ Wq, const float* __restrict__ Wk,
                     const float* __restrict__ Wv, const float* __restrict__ Wo,
                     const float* __restrict__ Wqn, const float* __restrict__ Wkbk,
                     const float* __restrict__ Wkbv) {
    int bid = blockIdx.x;
    const float* src; __nv_bfloat16 *dh, *dl;
    int c4pr, ostr, coff;
    if      (bid <  4096) {            src = hs;   dh = s_hs_h;    dl = s_hs_l;    c4pr = 512; ostr = 2048; coff = 0;    }
    else if (bid <  6144) { bid -= 4096;  src = kb;   dh = s_kb_h;    dl = s_kb_l;    c4pr = 512; ostr = 2048; coff = 0;    }
    else if (bid < 10240) { bid -= 6144;  src = Wq;   dh = s_wcomb_h; dl = s_wcomb_l; c4pr = 512; ostr = 5120; coff = 0;    }
    else if (bid < 14336) { bid -= 10240; src = Wqn;  dh = s_wcomb_h; dl = s_wcomb_l; c4pr = 512; ostr = 5120; coff = 2048; }
    else if (bid < 15360) { bid -= 14336; src = Wk;   dh = s_wcomb_h; dl = s_wcomb_l; c4pr = 128; ostr = 5120; coff = 4096; }
    else if (bid < 16384) { bid -= 15360; src = Wv;   dh = s_wcomb_h; dl = s_wcomb_l; c4pr = 128; ostr = 5120; coff = 4608; }
    else if (bid < 20480) { bid -= 16384; src = Wo;   dh = s_wo_h;    dl = s_wo_l;    c4pr = 512; ostr = 2048; coff = 0;    }
    else if (bid < 21504) { bid -= 20480; src = Wkbk; dh = s_wkb_h;   dl = s_wkb_l;   c4pr = 128; ostr = 1024; coff = 0;    }
    else                  { bid -= 21504; src = Wkbv; dh = s_wkb_h;   dl = s_wkb_l;   c4pr = 128; ostr = 1024; coff = 512;  }

    int i = bid * 256 + threadIdx.x;
    int r = i / c4pr, c4 = i % c4pr;
    float4 v = ((const float4*)src)[i];
    float vv[4] = {v.x, v.y, v.z, v.w};
    __nv_bfloat16 h[4], l[4];
    #pragma unroll
    for (int j = 0; j < 4; j++) {
        h[j] = __float2bfloat16_rn(vv[j]);
        l[j] = __float2bfloat16_rn(vv[j] - __bfloat162float(h[j]));
    }
    size_t ob = (size_t)r * ostr + coff + c4 * 4;
    *(__nv_bfloat162*)&dh[ob]     = __nv_bfloat162(h[0], h[1]);
    *(__nv_bfloat162*)&dh[ob + 2] = __nv_bfloat162(h[2], h[3]);
    *(__nv_bfloat162*)&dl[ob]     = __nv_bfloat162(l[0], l[1]);
    *(__nv_bfloat162*)&dl[ob + 2] = __nv_bfloat162(l[2], l[3]);
}

// ---------------- shared GEMM machinery ----------------
constexpr int GBK = 32, GSTG = 3;
constexpr int STAGE_BYTES = 32768;

__device__ __forceinline__ void gemm_issue_stage(
        uint32_t base, int tid,
        const __nv_bfloat16* Ah, const __nv_bfloat16* Al,
        const __nv_bfloat16* Bh, const __nv_bfloat16* Bl,
        int rb, int cb, int k0, int K, int N) {
    #pragma unroll
    for (int it = 0; it < 2; it++) {
        int i = tid + it * 256;
        int r = i >> 2, c = i & 3;
        uint32_t dst = base + r * 64 + (((c ^ ((r >> 1) & 3))) << 4);
        size_t so = (size_t)(rb + r) * K + k0 + c * 8;
        cp_async16(dst,        Ah + so);
        cp_async16(dst + 8192, Al + so);
    }
    #pragma unroll
    for (int it = 0; it < 2; it++) {
        int i = tid + it * 256;
        int r = i >> 4, cn = i & 15;
        uint32_t dst = base + 16384 + r * 256 + (((cn ^ (r & 7))) << 4);
        size_t so = (size_t)(k0 + r) * N + cb + cn * 8;
        cp_async16(dst,        Bh + so);
        cp_async16(dst + 8192, Bl + so);
    }
}

// mainloop macro-equivalent as device function computing acc for this CTA tile
__device__ __forceinline__ void gemm_mainloop(
        uint32_t sb, int tid, int lane, int wm, int wn,
        const __nv_bfloat16* Ah, const __nv_bfloat16* Al,
        const __nv_bfloat16* Bh, const __nv_bfloat16* Bl,
        int rb, int cb, int K, int N, float (&acc)[2][8][4]) {
    const int nk = K / GBK;
    gemm_issue_stage(sb, tid, Ah, Al, Bh, Bl, rb, cb, 0, K, N);
    asm volatile("cp.async.commit_group;\n" ::);
    if (nk > 1) {
        gemm_issue_stage(sb + STAGE_BYTES, tid, Ah, Al, Bh, Bl, rb, cb, GBK, K, N);
    }
    asm volatile("cp.async.commit_group;\n" ::);

    const int sub = lane >> 3, li = lane & 7;
    const int arow_off = ((sub & 1) ? 8 : 0) + li;
    const int akc_off  = (sub >> 1) ? 8 : 0;
    const int bk_off   = ((sub & 1) ? 8 : 0) + li;
    const int bn_off   = (sub >> 1) ? 8 : 0;

    for (int i = 0; i < nk; i++) {
        asm volatile("cp.async.wait_group 1;\n" ::);
        __syncthreads();
        const int st = i % GSTG;
        const uint32_t abase = sb + st * STAGE_BYTES;
        const uint32_t bbase = abase + 16384;
        if (i + 2 < nk)
            gemm_issue_stage(sb + ((i + 2) % GSTG) * STAGE_BYTES, tid,
                             Ah, Al, Bh, Bl, rb, cb, (i + 2) * GBK, K, N);
        asm volatile("cp.async.commit_group;\n" ::);

        #pragma unroll
        for (int kk = 0; kk < GBK; kk += 16) {
            unsigned bh[8][2], bl[8][2];
            #pragma unroll
            for (int np = 0; np < 4; np++) {
                int n0 = wn * 64 + np * 16;
                int k  = kk + bk_off;
                int n  = n0 + bn_off;
                uint32_t addr = bbase + k * 256 + ((((n >> 3) ^ (k & 7))) << 4);
                unsigned r_[4];
                LDSM4T(r_, addr);
                bh[np*2][0] = r_[0]; bh[np*2][1] = r_[1]; bh[np*2+1][0] = r_[2]; bh[np*2+1][1] = r_[3];
                LDSM4T(r_, addr + 8192);
                bl[np*2][0] = r_[0]; bl[np*2][1] = r_[1]; bl[np*2+1][0] = r_[2]; bl[np*2+1][1] = r_[3];
            }
            #pragma unroll
            for (int mt = 0; mt < 2; mt++) {
                int r0 = wm * 32 + mt * 16;
                int row  = r0 + arow_off;
                int kcol = kk + akc_off;
                uint32_t aaddr = abase + row * 64 + ((((kcol >> 3) ^ ((row >> 1) & 3))) << 4);
                unsigned ah[4], al[4];
                LDSM4(ah, aaddr);
                LDSM4(al, aaddr + 8192);
                #pragma unroll
                for (int nt = 0; nt < 8; nt++) {
                    mma16816(acc[mt][nt], ah, bh[nt]);
                    mma16816(acc[mt][nt], ah, bl[nt]);
                    mma16816(acc[mt][nt], al, bh[nt]);
                }
            }
        }
        __syncthreads();
    }
}

// RoPE on one mt-slice of accumulators (head-aligned 64-wide warp tile)
__device__ __forceinline__ void rope_acc(float (&a)[8][4], int p0, int p1, int tig,
                                         const float* __restrict__ cosT,
                                         const float* __restrict__ sinT) {
    #pragma unroll
    for (int nt = 0; nt < 4; nt++) {
        const int d0 = nt * 8 + 2 * tig;
        float2 c0l = *(const float2*)&cosT[p0 + d0];
        float2 s0l = *(const float2*)&sinT[p0 + d0];
        float2 c0h = *(const float2*)&cosT[p0 + d0 + 32];
        float2 s0h = *(const float2*)&sinT[p0 + d0 + 32];
        float2 c1l = *(const float2*)&cosT[p1 + d0];
        float2 s1l = *(const float2*)&sinT[p1 + d0];
        float2 c1h = *(const float2*)&cosT[p1 + d0 + 32];
        float2 s1h = *(const float2*)&sinT[p1 + d0 + 32];
        float x1, x2;
        x1 = a[nt][0]; x2 = a[nt+4][0];
        a[nt][0]   = x1 * c0l.x - x2 * s0l.x;
        a[nt+4][0] = x2 * c0h.x + x1 * s0h.x;
        x1 = a[nt][1]; x2 = a[nt+4][1];
        a[nt][1]   = x1 * c0l.y - x2 * s0l.y;
        a[nt+4][1] = x2 * c0h.y + x1 * s0h.y;
        x1 = a[nt][2]; x2 = a[nt+4][2];
        a[nt][2]   = x1 * c1l.x - x2 * s1l.x;
        a[nt+4][2] = x2 * c1h.x + x1 * s1h.x;
        x1 = a[nt][3]; x2 = a[nt+4][3];
        a[nt][3]   = x1 * c1l.y - x2 * s1l.y;
        a[nt+4][3] = x2 * c1h.y + x1 * s1h.y;
    }
}

__device__ __forceinline__ void split_write(__nv_bfloat16* Oh, __nv_bfloat16* Ol,
                                            size_t off, float a, float b) {
    __nv_bfloat162 h = __floats2bfloat162_rn(a, b);
    float2 f = __bfloat1622float2(h);
    __nv_bfloat162 l = __floats2bfloat162_rn(a - f.x, b - f.y);
    *(__nv_bfloat162*)&Oh[off] = h;
    *(__nv_bfloat162*)&Ol[off] = l;
}

// ---------------- merged projection GEMM (proj 640 CTAs + kbkv 64 CTAs) ----------------
__global__ __launch_bounds__(256)
void proj_gemm(const int* __restrict__ pos,
               const float* __restrict__ cosT, const float* __restrict__ sinT) {
    extern __shared__ char smem[];
    uint32_t sb = (uint32_t)__cvta_generic_to_shared(smem);
    const int tid = threadIdx.x, lane = tid & 31, wid = tid >> 5;
    const int wm = wid >> 1, wn = wid & 1;
    const int gid = lane >> 2, tig = lane & 3;

    const bool iskb = blockIdx.x >= 640;
    int bx, by, N;
    const __nv_bfloat16 *Ah, *Al, *Bh, *Bl;
    if (!iskb) {
        bx = blockIdx.x % 40; by = blockIdx.x / 40; N = 5120;
        Ah = s_hs_h; Al = s_hs_l; Bh = s_wcomb_h; Bl = s_wcomb_l;
    } else {
        int idx = blockIdx.x - 640;
        bx = idx % 8; by = idx / 8; N = 1024;
        Ah = s_kb_h; Al = s_kb_l; Bh = s_wkb_h; Bl = s_wkb_l;
    }
    const int rb = by * 128, cb = bx * 128;

    float acc[2][8][4];
    #pragma unroll
    for (int mt = 0; mt < 2; mt++)
        #pragma unroll
        for (int nt = 0; nt < 8; nt++)
            #pragma unroll
            for (int i = 0; i < 4; i++) acc[mt][nt][i] = 0.f;

    gemm_mainloop(sb, tid, lane, wm, wn, Ah, Al, Bh, Bl, rb, cb, CHID, N, acc);

    // ---- region epilogue ----
    const int colbase = cb + wn * 64;
    #pragma unroll
    for (int mt = 0; mt < 2; mt++) {
        const int row0 = rb + wm * 32 + mt * 16 + gid;
        const int row1 = row0 + 8;
        if (iskb) {
            #pragma unroll
            for (int nt = 0; nt < 8; nt++) {
                const int col = colbase + nt * 8 + tig * 2;
                *(float2*)&g_kbkv[(size_t)row0 * 1024 + col] = make_float2(acc[mt][nt][0], acc[mt][nt][1]);
                *(float2*)&g_kbkv[(size_t)row1 * 1024 + col] = make_float2(acc[mt][nt][2], acc[mt][nt][3]);
                split_write(s_kbkvh, s_kbkvl, (size_t)row0 * 1024 + col, acc[mt][nt][0], acc[mt][nt][1]);
                split_write(s_kbkvh, s_kbkvl, (size_t)row1 * 1024 + col, acc[mt][nt][2], acc[mt][nt][3]);
            }
        } else if (colbase < 2048) {
            // Q: rope + L2E split
            rope_acc(acc[mt], pos[row0] * 64, pos[row1] * 64, tig, cosT, sinT);
            #pragma unroll
            for (int nt = 0; nt < 8; nt++) {
                const int col = colbase + nt * 8 + tig * 2;
                split_write(s_qh, s_ql, (size_t)row0 * 2048 + col,
                            acc[mt][nt][0] * SCALE_L2E, acc[mt][nt][1] * SCALE_L2E);
                split_write(s_qh, s_ql, (size_t)row1 * 2048 + col,
                            acc[mt][nt][2] * SCALE_L2E, acc[mt][nt][3] * SCALE_L2E);
            }
        } else if (colbase < 4096) {
            // KBQ: f32 + L2E split
            #pragma unroll
            for (int nt = 0; nt < 8; nt++) {
                const int col = colbase - 2048 + nt * 8 + tig * 2;
                *(float2*)&g_kbq[(size_t)row0 * 2048 + col] = make_float2(acc[mt][nt][0], acc[mt][nt][1]);
                *(float2*)&g_kbq[(size_t)row1 * 2048 + col] = make_float2(acc[mt][nt][2], acc[mt][nt][3]);
                split_write(s_kbqh, s_kbql, (size_t)row0 * 2048 + col,
                            acc[mt][nt][0] * SCALE_L2E, acc[mt][nt][1] * SCALE_L2E);
                split_write(s_kbqh, s_kbql, (size_t)row1 * 2048 + col,
                            acc[mt][nt][2] * SCALE_L2E, acc[mt][nt][3] * SCALE_L2E);
            }
        } else {
            // KV: rope on k half only
            if (colbase < 4608)
                rope_acc(acc[mt], pos[row0] * 64, pos[row1] * 64, tig, cosT, sinT);
            #pragma unroll
            for (int nt = 0; nt < 8; nt++) {
                const int col = colbase - 4096 + nt * 8 + tig * 2;
                split_write(s_kvh, s_kvl, (size_t)row0 * 1024 + col, acc[mt][nt][0], acc[mt][nt][1]);
                split_write(s_kvh, s_kvl, (size_t)row1 * 1024 + col, acc[mt][nt][2], acc[mt][nt][3]);
            }
        }
    }
}

// ---------------- output GEMM (attn_out @ Wo -> fp32 out) ----------------
__global__ __launch_bounds__(256)
void wo_gemm(float* __restrict__ Cf, int M, int N, int K) {
    extern __shared__ char smem[];
    uint32_t sb = (uint32_t)__cvta_generic_to_shared(smem);
    const int tid = threadIdx.x, lane = tid & 31, wid = tid >> 5;
    const int wm = wid >> 1, wn = wid & 1;
    const int gid = lane >> 2, tig = lane & 3;
    const int rb = blockIdx.y * 128, cb = blockIdx.x * 128;

    float acc[2][8][4];
    #pragma unroll
    for (int mt = 0; mt < 2; mt++)
        #pragma unroll
        for (int nt = 0; nt < 8; nt++)
            #pragma unroll
            for (int i = 0; i < 4; i++) acc[mt][nt][i] = 0.f;

    gemm_mainloop(sb, tid, lane, wm, wn, s_at_h, s_at_l, s_wo_h, s_wo_l, rb, cb, K, N, acc);

    #pragma unroll
    for (int mt = 0; mt < 2; mt++) {
        int r = rb + wm * 32 + mt * 16;
        #pragma unroll
        for (int nt = 0; nt < 8; nt++) {
            int c = cb + wn * 64 + nt * 8 + tig * 2;
            *(float2*)&Cf[(size_t)(r + gid    ) * N + c] = make_float2(acc[mt][nt][0], acc[mt][nt][1]);
            *(float2*)&Cf[(size_t)(r + gid + 8) * N + c] = make_float2(acc[mt][nt][2], acc[mt][nt][3]);
        }
    }
}

// ---------------- KB selection ----------------
__global__ void qsum_partial_kernel() {
    int b  = blockIdx.x, ch = blockIdx.y;
    int c  = threadIdx.x;
    int kh = c / CHD, dd = c % CHD;
    float s = 0.f;
    for (int q = ch * 64; q < ch * 64 + 64; q++) {
        const float* row = g_kbq + (size_t)(b * CQ + q) * (CNH * CHD);
        #pragma unroll
        for (int g = 0; g < CG; g++) s += row[(kh * CG + g) * CHD + dd];
    }
    g_qsum_part[(b * 16 + ch) * 512 + c] = s;
}
__global__ void qsum_combine_kernel() {
    int b = blockIdx.x, c = threadIdx.x;
    float s = 0.f;
    #pragma unroll
    for (int ch = 0; ch < 16; ch++) s += g_qsum_part[(b * 16 + ch) * 512 + c];
    g_qsum[b * 512 + c] = s;
}
__global__ void scores_kernel() {
    int gw = blockIdx.x * 8 + (threadIdx.x >> 5);
    int l  = threadIdx.x & 31;
    int b  = gw >> 9, n = gw & 511;
    const float* kr = g_kbkv + (size_t)(b * CKB + n) * 1024;
    const float* qs = g_qsum + b * 512;
    float s = 0.f;
    #pragma unroll
    for (int i = l; i < 512; i += 32) s = fmaf(kr[i], qs[i], s);
    #pragma unroll
    for (int o = 16; o > 0; o >>= 1) s += __shfl_xor_sync(0xffffffffu, s, o);
    if (l == 0) g_scores[b * CKB + n] = s;
}
__global__ void topk_kernel() {
    int b = blockIdx.x, l = threadIdx.x;
    __shared__ float sv[CKB];
    for (int i = l; i < CKB; i += 32) sv[i] = g_scores[b * CKB + i];
    __syncwarp();
    for (int t = 0; t < CTOPK; t++) {
        float v = -3.0e38f; int idx = 0x7fffffff;
        for (int i = l; i < CKB; i += 32) {
            float x = sv[i];
            if (x > v || (x == v && i < idx)) { v = x; idx = i; }
        }
        #pragma unroll
        for (int o = 16; o > 0; o >>= 1) {
            float ov = __shfl_xor_sync(0xffffffffu, v, o);
            int   oi = __shfl_xor_sync(0xffffffffu, idx, o);
            if (ov > v || (ov == v && oi < idx)) { v = ov; idx = oi; }
        }
        if (l == 0) { g_topidx[b * CTOPK + t] = idx; sv[idx] = -3.0e38f; }
        __syncwarp();
    }
}

// ---------------- tensor-core fused flash attention ----------------
constexpr int ATT_SMEM = 16384 + 2 * 32768;

__device__ __forceinline__ void attn_load_tile(uint32_t st, int b, int kh, int ph2, int t, int tid) {
    for (int i = tid; i < 512; i += 128) {
        int r = i >> 3, c = i & 7;
        int kg = t * 64 + r;
        const __nv_bfloat16 *H, *L;
        size_t base;
        if (ph2 == 0) {
            int n = (kg < CTOPK) ? g_topidx[b * CTOPK + kg] : 0;
            base = (size_t)(b * CKB + n) * 1024 + kh * 64;
            H = s_kbkvh; L = s_kbkvl;
        } else {
            base = (size_t)(b * CQ + kg) * 1024 + kh * 64;
            H = s_kvh; L = s_kvl;
        }
        uint32_t d = st + r * 128 + ((c ^ (r & 7)) << 4);
        cp_async16(d,         H + base + c * 8);
        cp_async16(d + 8192,  L + base + c * 8);
        cp_async16(d + 16384, H + base + 512 + c * 8);
        cp_async16(d + 24576, L + base + 512 + c * 8);
    }
}

__global__ __launch_bounds__(128) void attn_tc_kernel() {
    extern __shared__ char asmem[];
    uint32_t sq = (uint32_t)__cvta_generic_to_shared(asmem);
    const int tid = threadIdx.x, lane = tid & 31, w = tid >> 5;
    const int gid = lane >> 2, tig = lane & 3;
    const int sub = lane >> 3, li = lane & 7;
    const int qt = blockIdx.x, h = blockIdx.y, b = blockIdx.z;
    const int kh = h >> 2;
    const int q0 = qt * 64;

    float m0 = -1e30f, m1 = -1e30f, l0 = 0.f, l1 = 0.f;
    float oacc[8][4];
    #pragma unroll
    for (int nt = 0; nt < 8; nt++)
        #pragma unroll
        for (int c = 0; c < 4; c++) oacc[nt][c] = 0.f;

    for (int ph2 = 0; ph2 < 2; ph2++) {
        __syncthreads();
        const __nv_bfloat16* Qh = ph2 ? s_qh : s_kbqh;
        const __nv_bfloat16* Ql = ph2 ? s_ql : s_kbql;
        for (int i = tid; i < 512; i += 128) {
            int r = i >> 3, c = i & 7;
            uint32_t dst = sq + r * 128 + ((c ^ (r & 7)) << 4);
            size_t src = (size_t)(b * CQ + q0 + r) * 2048 + h * 64 + c * 8;
            cp_async16(dst,        Qh + src);
            cp_async16(dst + 8192, Ql + src);
        }
        const int ntiles = ph2 ? (qt + 1) : 2;
        attn_load_tile(sq + 16384, b, kh, ph2, 0, tid);
        asm volatile("cp.async.commit_group;\n" ::);

        for (int t = 0; t < ntiles; t++) {
            asm volatile("cp.async.wait_group 0;\n" ::);
            __syncthreads();
            if (t + 1 < ntiles) {
                attn_load_tile(sq + 16384 + ((t + 1) & 1) * 32768, b, kh, ph2, t + 1, tid);
                asm volatile("cp.async.commit_group;\n" ::);
            }
            const uint32_t stK = sq + 16384 + (t & 1) * 32768;
            const uint32_t stV = stK + 16384;

            float sacc[8][4];
            #pragma unroll
            for (int nt = 0; nt < 8; nt++)
                #pragma unroll
                for (int c = 0; c < 4; c++) sacc[nt][c] = 0.f;

            #pragma unroll
            for (int k16 = 0; k16 < 4; k16++) {
                int kk = k16 * 16;
                unsigned qa_h[4], qa_l[4];
                {
                    int row = w * 16 + (sub & 1) * 8 + li;
                    int ch  = (kk >> 3) + (sub >> 1);
                    uint32_t a = sq + row * 128 + ((ch ^ (row & 7)) << 4);
                    LDSM4(qa_h, a);
                    LDSM4(qa_l, a + 8192);
                }
                unsigned kb_h[8][2], kb_l[8][2];
                #pragma unroll
                for (int nt2 = 0; nt2 < 4; nt2++) {
                    int n  = nt2 * 16 + (sub >> 1) * 8 + li;
                    int ch = (kk >> 3) + (sub & 1);
                    uint32_t a = stK + n * 128 + ((ch ^ (n & 7)) << 4);
                    unsigned r_[4];
                    LDSM4(r_, a);
                    kb_h[nt2*2][0] = r_[0]; kb_h[nt2*2][1] = r_[1];
                    kb_h[nt2*2+1][0] = r_[2]; kb_h[nt2*2+1][1] = r_[3];
                    LDSM4(r_, a + 8192);
                    kb_l[nt2*2][0] = r_[0]; kb_l[nt2*2][1] = r_[1];
                    kb_l[nt2*2+1][0] = r_[2]; kb_l[nt2*2+1][1] = r_[3];
                }
                #pragma unroll
                for (int nt = 0; nt < 8; nt++) {
                    mma16816(sacc[nt], qa_h, kb_h[nt]);
                    mma16816(sacc[nt], qa_h, kb_l[nt]);
                    mma16816(sacc[nt], qa_l, kb_h[nt]);
                }
            }

            if (ph2 == 0) {
                #pragma unroll
                for (int nt = 0; nt < 8; nt++) {
                    int kg = t * 64 + nt * 8 + 2 * tig;
                    sacc[nt][0] = (kg     < CTOPK) ? sacc[nt][0] + KB_B2 : -1e30f;
                    sacc[nt][1] = (kg + 1 < CTOPK) ? sacc[nt][1] + KB_B2 : -1e30f;
                    sacc[nt][2] = (kg     < CTOPK) ? sacc[nt][2] + KB_B2 : -1e30f;
                    sacc[nt][3] = (kg + 1 < CTOPK) ? sacc[nt][3] + KB_B2 : -1e30f;
                }
            } else if (t == qt) {
                int rq0 = q0 + w * 16 + gid, rq1 = rq0 + 8;
                #pragma unroll
                for (int nt = 0; nt < 8; nt++) {
                    int kg = t * 64 + nt * 8 + 2 * tig;
                    if (kg     > rq0) sacc[nt][0] = -1e30f;
                    if (kg + 1 > rq0) sacc[nt][1] = -1e30f;
                    if (kg     > rq1) sacc[nt][2] = -1e30f;
                    if (kg + 1 > rq1) sacc[nt][3] = -1e30f;
                }
            }

            float mx0 = -1e30f, mx1 = -1e30f;
            #pragma unroll
            for (int nt = 0; nt < 8; nt++) {
                mx0 = fmaxf(mx0, fmaxf(sacc[nt][0], sacc[nt][1]));
                mx1 = fmaxf(mx1, fmaxf(sacc[nt][2], sacc[nt][3]));
            }
            mx0 = fmaxf(mx0, __shfl_xor_sync(0xffffffffu, mx0, 1));
            mx0 = fmaxf(mx0, __shfl_xor_sync(0xffffffffu, mx0, 2));
            mx1 = fmaxf(mx1, __shfl_xor_sync(0xffffffffu, mx1, 1));
            mx1 = fmaxf(mx1, __shfl_xor_sync(0xffffffffu, mx1, 2));
            float mn0 = fmaxf(m0, mx0), mn1 = fmaxf(m1, mx1);
            float cr0 = fexp2(m0 - mn0), cr1 = fexp2(m1 - mn1);
            float sum0 = 0.f, sum1 = 0.f;
            #pragma unroll
            for (int nt = 0; nt < 8; nt++) {
                sacc[nt][0] = fexp2(sacc[nt][0] - mn0);
                sacc[nt][1] = fexp2(sacc[nt][1] - mn0);
                sacc[nt][2] = fexp2(sacc[nt][2] - mn1);
                sacc[nt][3] = fexp2(sacc[nt][3] - mn1);
                sum0 += sacc[nt][0] + sacc[nt][1];
                sum1 += sacc[nt][2] + sacc[nt][3];
                oacc[nt][0] *= cr0; oacc[nt][1] *= cr0;
                oacc[nt][2] *= cr1; oacc[nt][3] *= cr1;
            }
            sum0 += __shfl_xor_sync(0xffffffffu, sum0, 1);
            sum0 += __shfl_xor_sync(0xffffffffu, sum0, 2);
            sum1 += __shfl_xor_sync(0xffffffffu, sum1, 1);
            sum1 += __shfl_xor_sync(0xffffffffu, sum1, 2);
            l0 = l0 * cr0 + sum0;
            l1 = l1 * cr1 + sum1;
            m0 = mn0; m1 = mn1;

            #pragma unroll
            for (int j = 0; j < 4; j++) {
                unsigned pa_h[4], pa_l[4];
                #pragma unroll
                for (int half = 0; half < 2; half++) {
                    float x0 = sacc[2*j+half][0], x1 = sacc[2*j+half][1];
                    float x2 = sacc[2*j+half][2], x3 = sacc[2*j+half][3];
                    __nv_bfloat162 hA = __floats2bfloat162_rn(x0, x1);
                    __nv_bfloat162 hB = __floats2bfloat162_rn(x2, x3);
                    float2 fA = __bfloat1622float2(hA), fB = __bfloat1622float2(hB);
                    __nv_bfloat162 lA = __floats2bfloat162_rn(x0 - fA.x, x1 - fA.y);
                    __nv_bfloat162 lB = __floats2bfloat162_rn(x2 - fB.x, x3 - fB.y);
                    pa_h[half*2]     = *(unsigned*)&hA;
                    pa_h[half*2 + 1] = *(unsigned*)&hB;
                    pa_l[half*2]     = *(unsigned*)&lA;
                    pa_l[half*2 + 1] = *(unsigned*)&lB;
                }
                unsigned vb_h[8][2], vb_l[8][2];
                #pragma unroll
                for (int nt2 = 0; nt2 < 4; nt2++) {
                    int k  = j * 16 + (sub & 1) * 8 + li;
                    int ch = nt2 * 2 + (sub >> 1);
                    uint32_t a = stV + k * 128 + ((ch ^ (k & 7)) << 4);
                    unsigned r_[4];
                    LDSM4T(r_, a);
                    vb_h[nt2*2][0] = r_[0]; vb_h[nt2*2][1] = r_[1];
                    vb_h[nt2*2+1][0] = r_[2]; vb_h[nt2*2+1][1] = r_[3];
                    LDSM4T(r_, a + 8192);
                    vb_l[nt2*2][0] = r_[0]; vb_l[nt2*2][1] = r_[1];
                    vb_l[nt2*2+1][0] = r_[2]; vb_l[nt2*2+1][1] = r_[3];
                }
                #pragma unroll
                for (int nt = 0; nt < 8; nt++) {
                    mma16816(oacc[nt], pa_h, vb_h[nt]);
                    mma16816(oacc[nt], pa_h, vb_l[nt]);
                    mma16816(oacc[nt], pa_l, vb_h[nt]);
                }
            }
        }
    }

    float i0 = 1.f / l0, i1 = 1.f / l1;
    size_t row0 = (size_t)(b * CQ + q0 + w * 16 + gid) * 2048;
    size_t row1 = row0 + 8 * 2048;
    #pragma unroll
    for (int nt = 0; nt < 8; nt++) {
        int col = h * 64 + nt * 8 + 2 * tig;
        split_write(s_at_h, s_at_l, row0 + col, oacc[nt][0] * i0, oacc[nt][1] * i0);
        split_write(s_at_h, s_at_l, row1 + col, oacc[nt][2] * i1, oacc[nt][3] * i1);
    }
}

// ---------------- launch ----------------
extern "C" void kernel_launch(void* const* d_in, const int* in_sizes, int n_in,
                              void* d_out, int out_size) {
    const float* hs   = (const float*)d_in[0];
    const float* kb   = (const float*)d_in[1];
    const float* Wq   = (const float*)d_in[2];
    const float* Wk   = (const float*)d_in[3];
    const float* Wv   = (const float*)d_in[4];
    const float* Wo   = (const float*)d_in[5];
    const float* Wqn  = (const float*)d_in[6];
    const float* Wkbk = (const float*)d_in[7];
    const float* Wkbv = (const float*)d_in[8];
    const float* cosT = (const float*)d_in[9];
    const float* sinT = (const float*)d_in[10];
    const int*   pos  = (const int*)d_in[12];
    float* out = (float*)d_out;

    static int attr_set = 0;
    if (!attr_set) {
        cudaFuncSetAttribute(proj_gemm, cudaFuncAttributeMaxDynamicSharedMemorySize, GSTG * STAGE_BYTES);
        cudaFuncSetAttribute(wo_gemm,   cudaFuncAttributeMaxDynamicSharedMemorySize, GSTG * STAGE_BYTES);
        cudaFuncSetAttribute(attn_tc_kernel, cudaFuncAttributeMaxDynamicSharedMemorySize, ATT_SMEM);
        attr_set = 1;
    }

    const int M = CB * CQ;   // 2048
    const int SMEM = GSTG * STAGE_BYTES;

    // 1. all splits in one launch (22528 blocks)
    splitall_kernel<<<22528, 256>>>(hs, kb, Wq, Wk, Wv, Wo, Wqn, Wkbk, Wkbv);

    // 2. merged projection GEMM: [hs@(Wq|Wqn|Wk|Wv)] + [kb@(Wkbk|Wkbv)] in one launch
    proj_gemm<<<704, 256, SMEM>>>(pos, cosT, sinT);

    // 3. KB top-k selection
    qsum_partial_kernel<<<dim3(CB, 16), 512>>>();
    qsum_combine_kernel<<<CB, 512>>>();
    scores_kernel<<<(CB * CKB) / 8, 256>>>();
    topk_kernel<<<CB, 32>>>();

    // 4. attention
    attn_tc_kernel<<<dim3(CQ / 64, CNH, CB), 128, ATT_SMEM>>>();

    // 5. output projection
    wo_gemm<<<dim3(CHID/128, M/128), 256, SMEM>>>(out, M, CHID, CHID);
}